// round 15
// baseline (speedup 1.0000x reference)
#include <cuda_runtime.h>

#define Hdim 64
#define Wdim 64
#define HW 4096
#define NCH 256

// ---------------------------------------------------------------------------
// Identity copy of first 64 channels of each batch image.
// ---------------------------------------------------------------------------
__global__ void copy_id_kernel(const float* __restrict__ x, float* __restrict__ out) {
    long i = (long)blockIdx.x * blockDim.x + threadIdx.x;   // float4 index
    const long perN = 64L * (HW / 4);                       // float4 per batch (64 ch)
    long n = i / perN;
    long r = i - n * perN;
    const float4* src = (const float4*)(x + n * (long)NCH * HW);
    float4* dst = (float4*)(out + n * (long)NCH * HW);
    dst[r] = src[r];
}

// ---------------------------------------------------------------------------
// Grouped quantized conv: one block per (group, n). 4 in-ch -> 4 out-ch.
// Input tile (4 planes + halo) staged in SMEM; weights fake-quantized in SMEM.
// Each thread computes 8 consecutive pixels x 4 out channels.
// ---------------------------------------------------------------------------
template<int KH, int KW, int PH, int PW>
__global__ void __launch_bounds__(256, 2) conv_kernel(
    const float* __restrict__ x, const float* __restrict__ wgt,
    const float* __restrict__ bias, const float* __restrict__ sptr,
    float* __restrict__ out, int ch_off)
{
    constexpr int PADL = (PW + 3) & ~3;          // left pad, multiple of 4
    constexpr int SW   = PADL + Wdim + PADL;     // smem row stride (mult of 4)
    constexpr int SH   = Hdim + 2 * PH;
    constexpr int OFF  = PADL - PW;              // 0..3
    constexpr int NWGT = 16 * KH * KW;           // 4 oc * 4 ic * taps

    extern __shared__ float smem[];
    float* tile  = smem;                         // 4 * SH * SW
    float* swgt  = smem + 4 * SH * SW;           // NWGT  (layout [ic][ky][kx][oc])
    float* sbias = swgt + NWGT;                  // 4

    const int tid = threadIdx.x;
    const int g   = blockIdx.x;                  // group 0..15
    const int n   = blockIdx.y;                  // batch 0..63

    // ---- fake-quantize weights into smem ----
    const float s = *sptr;
    for (int i = tid; i < NWGT; i += 256) {
        int oc   = i & 3;
        int rest = i >> 2;
        int kx   = rest % KW;
        int ky   = (rest / KW) % KH;
        int ic   = rest / (KW * KH);
        float wv = wgt[((g * 4 + oc) * 4 + ic) * (KH * KW) + ky * KW + kx];
        float q  = rintf(wv / s);                       // round half-to-even, matches jnp.round
        q = fminf(7.0f, fmaxf(-8.0f, q));
        swgt[i] = q * s;
    }
    if (tid < 4) sbias[tid] = bias[g * 4 + tid];

    // ---- zero column halos ----
    if constexpr (PADL > 0) {
        constexpr int padF4 = (2 * PADL) / 4;           // float4 pad slots per row
        for (int i = tid; i < 4 * SH * padF4; i += 256) {
            int row = i / padF4, k = i - row * padF4;
            int col4 = (k < PADL / 4) ? k : (PADL + Wdim) / 4 + (k - PADL / 4);
            ((float4*)(tile + row * SW))[col4] = make_float4(0.f, 0.f, 0.f, 0.f);
        }
    }

    // ---- stage 4 input planes (with row halo zero-fill) ----
    const float* xin = x + ((long)n * NCH + ch_off + g * 4) * HW;
    {
        const int lane = tid & 15;                      // 16 float4 per row
        for (int t = tid >> 4; t < 4 * SH; t += 16) {
            int ic = t / SH, r = t - ic * SH;
            int gy = r - PH;
            float4 v = make_float4(0.f, 0.f, 0.f, 0.f);
            if (gy >= 0 && gy < Hdim)
                v = *(const float4*)(xin + ic * HW + gy * Wdim + lane * 4);
            *(float4*)(tile + (ic * SH + r) * SW + PADL + lane * 4) = v;
        }
    }
    __syncthreads();

    // ---- compute: 512 tasks (8 px each) per plane-set ----
    constexpr int NV4 = (OFF + KW + 7 + 3) / 4;         // float4s covering window
    const float4 b4 = *(const float4*)sbias;
    for (int task = tid; task < 512; task += 256) {
        int py  = task >> 3;
        int pxb = (task & 7) * 8;
        float acc[4][8];
        #pragma unroll
        for (int j = 0; j < 8; j++) {
            acc[0][j] = b4.x; acc[1][j] = b4.y; acc[2][j] = b4.z; acc[3][j] = b4.w;
        }
        #pragma unroll
        for (int ic = 0; ic < 4; ic++) {
            #pragma unroll
            for (int ky = 0; ky < KH; ky++) {
                const float* rowp = tile + (ic * SH + py + ky) * SW + pxb;
                float4 v[NV4];
                #pragma unroll
                for (int i = 0; i < NV4; i++) v[i] = ((const float4*)rowp)[i];
                const float* win = (const float*)v;
                #pragma unroll
                for (int kx = 0; kx < KW; kx++) {
                    float4 w4 = *(const float4*)&swgt[((ic * KH + ky) * KW + kx) * 4];
                    #pragma unroll
                    for (int j = 0; j < 8; j++) {
                        float xv = win[OFF + kx + j];
                        acc[0][j] = fmaf(w4.x, xv, acc[0][j]);
                        acc[1][j] = fmaf(w4.y, xv, acc[1][j]);
                        acc[2][j] = fmaf(w4.z, xv, acc[2][j]);
                        acc[3][j] = fmaf(w4.w, xv, acc[3][j]);
                    }
                }
            }
        }
        float* obase = out + ((long)n * NCH + ch_off + g * 4) * HW + py * Wdim + pxb;
        #pragma unroll
        for (int oc = 0; oc < 4; oc++) {
            float* op = obase + oc * HW;
            *(float4*)(op)     = make_float4(acc[oc][0], acc[oc][1], acc[oc][2], acc[oc][3]);
            *(float4*)(op + 4) = make_float4(acc[oc][4], acc[oc][5], acc[oc][6], acc[oc][7]);
        }
    }
}

// ---------------------------------------------------------------------------

static inline int conv_smem_bytes(int KH, int KW, int PH, int PW) {
    int PADL = (PW + 3) & ~3;
    int SW = PADL + Wdim + PADL;
    int SH = Hdim + 2 * PH;
    return (4 * SH * SW + 16 * KH * KW + 4) * (int)sizeof(float);
}

extern "C" void kernel_launch(void* const* d_in, const int* in_sizes, int n_in,
                              void* d_out, int out_size) {
    (void)in_sizes; (void)n_in; (void)out_size;
    const float* x    = (const float*)d_in[0];
    const float* w_hw = (const float*)d_in[1];
    const float* b_hw = (const float*)d_in[2];
    const float* s_hw = (const float*)d_in[3];
    const float* w_w  = (const float*)d_in[4];
    const float* b_w  = (const float*)d_in[5];
    const float* s_w  = (const float*)d_in[6];
    const float* w_h  = (const float*)d_in[7];
    const float* b_h  = (const float*)d_in[8];
    const float* s_h  = (const float*)d_in[9];
    float* out = (float*)d_out;

    const int smem_h  = conv_smem_bytes(11, 1, 5, 0);
    const int smem_w  = conv_smem_bytes(1, 11, 0, 5);
    const int smem_hw = conv_smem_bytes(3, 3, 1, 1);

    cudaFuncSetAttribute(conv_kernel<11, 1, 5, 0>,
                         cudaFuncAttributeMaxDynamicSharedMemorySize, smem_h);
    cudaFuncSetAttribute(conv_kernel<1, 11, 0, 5>,
                         cudaFuncAttributeMaxDynamicSharedMemorySize, smem_w);
    cudaFuncSetAttribute(conv_kernel<3, 3, 1, 1>,
                         cudaFuncAttributeMaxDynamicSharedMemorySize, smem_hw);

    // identity copy: 64 n * 64 ch * 4096 px / 4 = 4,194,304 float4
    copy_id_kernel<<<16384, 256>>>(x, out);

    dim3 grid(16, 64);
    conv_kernel<11, 1, 5, 0><<<grid, 256, smem_h>>>(x, w_h, b_h, s_h, out, 64);
    conv_kernel<1, 11, 0, 5><<<grid, 256, smem_w>>>(x, w_w, b_w, s_w, out, 128);
    conv_kernel<3, 3, 1, 1><<<grid, 256, smem_hw>>>(x, w_hw, b_hw, s_hw, out, 192);
}

// round 16
// speedup vs baseline: 1.0024x; 1.0024x over previous
#include <cuda_runtime.h>

#define Hdim 64
#define Wdim 64
#define HW 4096
#define NCH 256

// ---------------------------------------------------------------------------
// Identity copy of first 64 channels of each batch image.
// ---------------------------------------------------------------------------
__global__ void copy_id_kernel(const float* __restrict__ x, float* __restrict__ out) {
    long i = (long)blockIdx.x * blockDim.x + threadIdx.x;   // float4 index
    const long perN = 64L * (HW / 4);                       // float4 per batch (64 ch)
    long n = i / perN;
    long r = i - n * perN;
    const float4* src = (const float4*)(x + n * (long)NCH * HW);
    float4* dst = (float4*)(out + n * (long)NCH * HW);
    dst[r] = src[r];
}

// ---------------------------------------------------------------------------
// Grouped quantized conv: one block per (group, n). 4 in-ch -> 4 out-ch.
// Input tile (4 planes + halo) staged in SMEM; weights fake-quantized in SMEM.
// Each thread computes 8 consecutive pixels x 4 out channels.
// ---------------------------------------------------------------------------
template<int KH, int KW, int PH, int PW>
__global__ void __launch_bounds__(256, 2) conv_kernel(
    const float* __restrict__ x, const float* __restrict__ wgt,
    const float* __restrict__ bias, const float* __restrict__ sptr,
    float* __restrict__ out, int ch_off)
{
    constexpr int PADL = (PW + 3) & ~3;          // left pad, multiple of 4
    constexpr int SW   = PADL + Wdim + PADL;     // smem row stride (mult of 4)
    constexpr int SH   = Hdim + 2 * PH;
    constexpr int OFF  = PADL - PW;              // 0..3
    constexpr int NWGT = 16 * KH * KW;           // 4 oc * 4 ic * taps

    extern __shared__ float smem[];
    float* tile  = smem;                         // 4 * SH * SW
    float* swgt  = smem + 4 * SH * SW;           // NWGT  (layout [ic][ky][kx][oc])
    float* sbias = swgt + NWGT;                  // 4

    const int tid = threadIdx.x;
    const int g   = blockIdx.x;                  // group 0..15
    const int n   = blockIdx.y;                  // batch 0..63

    // ---- fake-quantize weights into smem ----
    const float s = *sptr;
    for (int i = tid; i < NWGT; i += 256) {
        int oc   = i & 3;
        int rest = i >> 2;
        int kx   = rest % KW;
        int ky   = (rest / KW) % KH;
        int ic   = rest / (KW * KH);
        float wv = wgt[((g * 4 + oc) * 4 + ic) * (KH * KW) + ky * KW + kx];
        float q  = rintf(wv / s);                       // round half-to-even, matches jnp.round
        q = fminf(7.0f, fmaxf(-8.0f, q));
        swgt[i] = q * s;
    }
    if (tid < 4) sbias[tid] = bias[g * 4 + tid];

    // ---- zero column halos ----
    if constexpr (PADL > 0) {
        constexpr int padF4 = (2 * PADL) / 4;           // float4 pad slots per row
        for (int i = tid; i < 4 * SH * padF4; i += 256) {
            int row = i / padF4, k = i - row * padF4;
            int col4 = (k < PADL / 4) ? k : (PADL + Wdim) / 4 + (k - PADL / 4);
            ((float4*)(tile + row * SW))[col4] = make_float4(0.f, 0.f, 0.f, 0.f);
        }
    }

    // ---- stage 4 input planes (with row halo zero-fill) ----
    const float* xin = x + ((long)n * NCH + ch_off + g * 4) * HW;
    {
        const int lane = tid & 15;                      // 16 float4 per row
        for (int t = tid >> 4; t < 4 * SH; t += 16) {
            int ic = t / SH, r = t - ic * SH;
            int gy = r - PH;
            float4 v = make_float4(0.f, 0.f, 0.f, 0.f);
            if (gy >= 0 && gy < Hdim)
                v = *(const float4*)(xin + ic * HW + gy * Wdim + lane * 4);
            *(float4*)(tile + (ic * SH + r) * SW + PADL + lane * 4) = v;
        }
    }
    __syncthreads();

    // ---- compute: 512 tasks (8 px each) per plane-set ----
    constexpr int NV4 = (OFF + KW + 7 + 3) / 4;         // float4s covering window
    const float4 b4 = *(const float4*)sbias;
    for (int task = tid; task < 512; task += 256) {
        int py  = task >> 3;
        int pxb = (task & 7) * 8;
        float acc[4][8];
        #pragma unroll
        for (int j = 0; j < 8; j++) {
            acc[0][j] = b4.x; acc[1][j] = b4.y; acc[2][j] = b4.z; acc[3][j] = b4.w;
        }
        #pragma unroll
        for (int ic = 0; ic < 4; ic++) {
            #pragma unroll
            for (int ky = 0; ky < KH; ky++) {
                const float* rowp = tile + (ic * SH + py + ky) * SW + pxb;
                float4 v[NV4];
                #pragma unroll
                for (int i = 0; i < NV4; i++) v[i] = ((const float4*)rowp)[i];
                const float* win = (const float*)v;
                #pragma unroll
                for (int kx = 0; kx < KW; kx++) {
                    float4 w4 = *(const float4*)&swgt[((ic * KH + ky) * KW + kx) * 4];
                    #pragma unroll
                    for (int j = 0; j < 8; j++) {
                        float xv = win[OFF + kx + j];
                        acc[0][j] = fmaf(w4.x, xv, acc[0][j]);
                        acc[1][j] = fmaf(w4.y, xv, acc[1][j]);
                        acc[2][j] = fmaf(w4.z, xv, acc[2][j]);
                        acc[3][j] = fmaf(w4.w, xv, acc[3][j]);
                    }
                }
            }
        }
        float* obase = out + ((long)n * NCH + ch_off + g * 4) * HW + py * Wdim + pxb;
        #pragma unroll
        for (int oc = 0; oc < 4; oc++) {
            float* op = obase + oc * HW;
            *(float4*)(op)     = make_float4(acc[oc][0], acc[oc][1], acc[oc][2], acc[oc][3]);
            *(float4*)(op + 4) = make_float4(acc[oc][4], acc[oc][5], acc[oc][6], acc[oc][7]);
        }
    }
}

// ---------------------------------------------------------------------------

static inline int conv_smem_bytes(int KH, int KW, int PH, int PW) {
    int PADL = (PW + 3) & ~3;
    int SW = PADL + Wdim + PADL;
    int SH = Hdim + 2 * PH;
    return (4 * SH * SW + 16 * KH * KW + 4) * (int)sizeof(float);
}

extern "C" void kernel_launch(void* const* d_in, const int* in_sizes, int n_in,
                              void* d_out, int out_size) {
    (void)in_sizes; (void)n_in; (void)out_size;
    const float* x    = (const float*)d_in[0];
    const float* w_hw = (const float*)d_in[1];
    const float* b_hw = (const float*)d_in[2];
    const float* s_hw = (const float*)d_in[3];
    const float* w_w  = (const float*)d_in[4];
    const float* b_w  = (const float*)d_in[5];
    const float* s_w  = (const float*)d_in[6];
    const float* w_h  = (const float*)d_in[7];
    const float* b_h  = (const float*)d_in[8];
    const float* s_h  = (const float*)d_in[9];
    float* out = (float*)d_out;

    const int smem_h  = conv_smem_bytes(11, 1, 5, 0);
    const int smem_w  = conv_smem_bytes(1, 11, 0, 5);
    const int smem_hw = conv_smem_bytes(3, 3, 1, 1);

    cudaFuncSetAttribute(conv_kernel<11, 1, 5, 0>,
                         cudaFuncAttributeMaxDynamicSharedMemorySize, smem_h);
    cudaFuncSetAttribute(conv_kernel<1, 11, 0, 5>,
                         cudaFuncAttributeMaxDynamicSharedMemorySize, smem_w);
    cudaFuncSetAttribute(conv_kernel<3, 3, 1, 1>,
                         cudaFuncAttributeMaxDynamicSharedMemorySize, smem_hw);

    // identity copy: 64 n * 64 ch * 4096 px / 4 = 4,194,304 float4
    copy_id_kernel<<<16384, 256>>>(x, out);

    dim3 grid(16, 64);
    conv_kernel<11, 1, 5, 0><<<grid, 256, smem_h>>>(x, w_h, b_h, s_h, out, 64);
    conv_kernel<1, 11, 0, 5><<<grid, 256, smem_w>>>(x, w_w, b_w, s_w, out, 128);
    conv_kernel<3, 3, 1, 1><<<grid, 256, smem_hw>>>(x, w_hw, b_hw, s_hw, out, 192);
}

// round 17
// speedup vs baseline: 1.5066x; 1.5030x over previous
#include <cuda_runtime.h>

#define Hdim 64
#define Wdim 64
#define HW 4096
#define NCH 256

typedef unsigned long long ull;

__device__ __forceinline__ ull pack2(float lo, float hi) {
    ull r;
    asm("mov.b64 %0, {%1,%2};" : "=l"(r) : "f"(lo), "f"(hi));
    return r;
}
__device__ __forceinline__ void unpack2(ull v, float& lo, float& hi) {
    asm("mov.b64 {%0,%1}, %2;" : "=f"(lo), "=f"(hi) : "l"(v));
}
__device__ __forceinline__ ull ffma2(ull a, ull b, ull c) {
    ull d;
    asm("fma.rn.f32x2 %0, %1, %2, %3;" : "=l"(d) : "l"(a), "l"(b), "l"(c));
    return d;
}

// ---------------------------------------------------------------------------
// Grouped quantized conv, one 16-row chunk of one (n, group) per block.
// 128 threads; each thread: 8 consecutive px (as 4 f32x2 pairs) x 4 oc.
// ---------------------------------------------------------------------------
template<int KH, int KW, int PH, int PW>
__device__ __forceinline__ void conv_impl(
    const float* __restrict__ x, const float* __restrict__ wgt,
    const float* __restrict__ bias, const float* __restrict__ sptr,
    float* __restrict__ out, int ch_off, int rem, float* smem)
{
    constexpr int PADL = (PW + 3) & ~3;
    constexpr int SW   = PADL + Wdim + PADL;
    constexpr int CH   = 16;                   // output rows per chunk
    constexpr int SHc  = CH + 2 * PH;          // staged rows
    constexpr int OFF  = PADL - PW;
    constexpr int TAPS = KH * KW;
    constexpr int NWGT = 16 * TAPS;            // 4oc*4ic*taps

    float* tile = smem;                        // 4 * SHc * SW floats
    float2* w2  = (float2*)(smem + 4 * SHc * SW);  // duplicated (w,w), [ic][ky][kx][oc]

    const int tid   = threadIdx.x;
    const int n     = rem >> 6;
    const int g     = (rem >> 2) & 15;
    const int chunk = rem & 3;

    // ---- fake-quantize weights, store duplicated pairs ----
    const float s = __ldg(sptr);
    for (int i = tid; i < NWGT; i += 128) {
        int oc   = i & 3;
        int rest = i >> 2;
        int kx   = rest % KW;
        int ky   = (rest / KW) % KH;
        int ic   = rest / TAPS;
        float wv = __ldg(&wgt[((g * 4 + oc) * 4 + ic) * TAPS + ky * KW + kx]);
        float q  = rintf(wv / s);
        q = fminf(7.0f, fmaxf(-8.0f, q));
        float v = q * s;
        w2[((ic * KH + ky) * KW + kx) * 4 + oc] = make_float2(v, v);
    }

    // ---- zero column halos ----
    if constexpr (PADL > 0) {
        constexpr int padF4 = (2 * PADL) / 4;
        for (int i = tid; i < 4 * SHc * padF4; i += 128) {
            int row = i / padF4, k = i - row * padF4;
            int col4 = (k < PADL / 4) ? k : (PADL + Wdim) / 4 + (k - PADL / 4);
            ((float4*)(tile + row * SW))[col4] = make_float4(0.f, 0.f, 0.f, 0.f);
        }
    }

    // ---- stage 4 input planes for this chunk (row-halo zero fill) ----
    const float* xin = x + ((long)n * NCH + ch_off + g * 4) * HW;
    const int y0 = chunk * CH - PH;
    {
        const int lane = tid & 15;             // 16 float4 per row
        for (int t = tid >> 4; t < 4 * SHc; t += 8) {
            int ic = t / SHc, r = t - ic * SHc;
            int gy = y0 + r;
            float4 v = make_float4(0.f, 0.f, 0.f, 0.f);
            if (gy >= 0 && gy < Hdim)
                v = *(const float4*)(xin + ic * HW + gy * Wdim + lane * 4);
            *(float4*)(tile + (ic * SHc + r) * SW + PADL + lane * 4) = v;
        }
    }
    __syncthreads();

    // ---- compute: tid -> (py, pxb), 8 px x 4 oc, packed f32x2 ----
    constexpr int NV4 = (OFF + KW + 7 + 3) / 4;
    const int py  = tid >> 3;
    const int pxb = (tid & 7) * 8;

    ull acc[4][4];
    #pragma unroll
    for (int oc = 0; oc < 4; oc++) {
        float b = __ldg(&bias[g * 4 + oc]);
        ull bb = pack2(b, b);
        #pragma unroll
        for (int k = 0; k < 4; k++) acc[oc][k] = bb;
    }

    #pragma unroll
    for (int ic = 0; ic < 4; ic++) {
        #pragma unroll
        for (int ky = 0; ky < KH; ky++) {
            const float* rowp = tile + (ic * SHc + py + ky) * SW + pxb;
            float4 v[NV4];
            #pragma unroll
            for (int i = 0; i < NV4; i++) v[i] = ((const float4*)rowp)[i];
            const float* win = (const float*)v;
            #pragma unroll
            for (int kx = 0; kx < KW; kx++) {
                const ulonglong2* wp =
                    (const ulonglong2*)(w2 + ((ic * KH + ky) * KW + kx) * 4);
                ulonglong2 wa = wp[0];         // (oc0 dup, oc1 dup)
                ulonglong2 wb = wp[1];         // (oc2 dup, oc3 dup)
                #pragma unroll
                for (int k = 0; k < 4; k++) {
                    ull xp = pack2(win[OFF + kx + 2 * k], win[OFF + kx + 2 * k + 1]);
                    acc[0][k] = ffma2(wa.x, xp, acc[0][k]);
                    acc[1][k] = ffma2(wa.y, xp, acc[1][k]);
                    acc[2][k] = ffma2(wb.x, xp, acc[2][k]);
                    acc[3][k] = ffma2(wb.y, xp, acc[3][k]);
                }
            }
        }
    }

    const int oy = chunk * CH + py;
    float* obase = out + ((long)n * NCH + ch_off + g * 4) * HW + oy * Wdim + pxb;
    #pragma unroll
    for (int oc = 0; oc < 4; oc++) {
        float r[8];
        #pragma unroll
        for (int k = 0; k < 4; k++) unpack2(acc[oc][k], r[2 * k], r[2 * k + 1]);
        float* op = obase + oc * HW;
        *(float4*)(op)     = make_float4(r[0], r[1], r[2], r[3]);
        *(float4*)(op + 4) = make_float4(r[4], r[5], r[6], r[7]);
    }
}

// ---------------------------------------------------------------------------
// Fused kernel: interleaved copy + 3 conv types.
// grid = 16384 blocks x 128 threads.
//   bid & 3 == 3  -> copy block   (c = bid>>2, 4096 blocks)
//   else          -> conv block   (ci = (bid>>2)*3 + (bid&3), 12288 blocks)
//                    type = ci % 3 (0: 11x1, 1: 1x11, 2: 3x3), rem = ci / 3
// ---------------------------------------------------------------------------
__global__ void __launch_bounds__(128, 6) fused_kernel(
    const float* __restrict__ x,
    const float* __restrict__ w_hw, const float* __restrict__ b_hw, const float* __restrict__ s_hw,
    const float* __restrict__ w_w,  const float* __restrict__ b_w,  const float* __restrict__ s_w,
    const float* __restrict__ w_h,  const float* __restrict__ b_h,  const float* __restrict__ s_h,
    float* __restrict__ out)
{
    extern __shared__ float smem[];
    const int bid = blockIdx.x;

    if ((bid & 3) == 3) {
        // identity copy: 64 ch per batch, 1024 float4 per block
        int c = bid >> 2;
        int n = c >> 6;
        long base = (long)n * (NCH * HW / 4) + (long)(c & 63) * 1024 + threadIdx.x;
        const float4* src = (const float4*)x;
        float4* dst = (float4*)out;
        #pragma unroll
        for (int k = 0; k < 8; k++) dst[base + k * 128] = src[base + k * 128];
        return;
    }

    int ci   = (bid >> 2) * 3 + (bid & 3);
    int type = ci % 3;
    int rem  = ci / 3;                         // 0..4095: n(6) g(4) chunk(2)

    if (type == 0)
        conv_impl<11, 1, 5, 0>(x, w_h, b_h, s_h, out, 64, rem, smem);
    else if (type == 1)
        conv_impl<1, 11, 0, 5>(x, w_w, b_w, s_w, out, 128, rem, smem);
    else
        conv_impl<3, 3, 1, 1>(x, w_hw, b_hw, s_hw, out, 192, rem, smem);
}

// ---------------------------------------------------------------------------

static inline int conv_smem_bytes(int KH, int KW, int PH, int PW) {
    int PADL = (PW + 3) & ~3;
    int SW = PADL + Wdim + PADL;
    int SHc = 16 + 2 * PH;
    return (4 * SHc * SW + 16 * KH * KW * 2) * (int)sizeof(float);
}

extern "C" void kernel_launch(void* const* d_in, const int* in_sizes, int n_in,
                              void* d_out, int out_size) {
    (void)in_sizes; (void)n_in; (void)out_size;
    const float* x    = (const float*)d_in[0];
    const float* w_hw = (const float*)d_in[1];
    const float* b_hw = (const float*)d_in[2];
    const float* s_hw = (const float*)d_in[3];
    const float* w_w  = (const float*)d_in[4];
    const float* b_w  = (const float*)d_in[5];
    const float* s_w  = (const float*)d_in[6];
    const float* w_h  = (const float*)d_in[7];
    const float* b_h  = (const float*)d_in[8];
    const float* s_h  = (const float*)d_in[9];
    float* out = (float*)d_out;

    int smem = conv_smem_bytes(11, 1, 5, 0);
    int s2   = conv_smem_bytes(1, 11, 0, 5);
    int s3   = conv_smem_bytes(3, 3, 1, 1);
    if (s2 > smem) smem = s2;
    if (s3 > smem) smem = s3;                  // ~28 KB, below 48 KB static limit

    fused_kernel<<<16384, 128, smem>>>(x,
                                       w_hw, b_hw, s_hw,
                                       w_w,  b_w,  s_w,
                                       w_h,  b_h,  s_h,
                                       out);
}